// round 4
// baseline (speedup 1.0000x reference)
#include <cuda_runtime.h>
#include <cstdint>

#define BB 8
#define CC 64
#define NN 16384
#define JJ 128      // 2 branches * 32 m * (cos,sin)
#define KP 64       // j-pairs (k-pairs in pass C)
#define NT 64       // n-tile
#define VSTRIDE 132 // padded row stride (floats) for basis tiles

// Inter-kernel scratch (static __device__ — no allocation)
__device__ float g_F[BB * CC * JJ];      // pass A output: [b][c][j]
__device__ float g_G[BB * KP * CC * 2];  // pass B output: [b][kp][o][(re,-im)*64]

// ---------- helpers ----------

// (sin(2*pi*t), cos(2*pi*t)) for t in [0,1): shift to [-pi,pi) for __sincosf accuracy
__device__ __forceinline__ void sc2pi(float t, float& s, float& c) {
    float a = fmaf(t, 6.28318530718f, -3.14159265359f);
    float ss, cc;
    __sincosf(a, &ss, &cc);
    s = -ss;
    c = -cc;
}

__device__ __forceinline__ unsigned long long pack2(float lo, float hi) {
    unsigned long long r;
    asm("mov.b64 %0, {%1, %2};" : "=l"(r) : "f"(lo), "f"(hi));
    return r;
}

__device__ __forceinline__ void unpack2(unsigned long long v, float& lo, float& hi) {
    asm("mov.b64 {%0, %1}, %2;" : "=f"(lo), "=f"(hi) : "l"(v));
}

// packed f32x2 FMA: d = a*b + d (lanewise)
__device__ __forceinline__ void ffma2(unsigned long long& d, unsigned long long a,
                                      unsigned long long b) {
    asm("fma.rn.f32x2 %0, %1, %2, %0;" : "+l"(d) : "l"(a), "l"(b));
}

// Fill one basis row segment: writes (cos,sin) of 2*pi*p*m for m = ms..ms+15.
// Returns values through smem writes done by caller pattern; here inlined per kernel.

// ---------- zero scratch ----------

__global__ void zeroF_kernel() {
    g_F[blockIdx.x * 256 + threadIdx.x] = 0.0f;
}

// ---------- Pass A: F[b,c,j] = sum_n x[b,c,n] * basis(x_in)[n,j] ----------
// grid (32 chunks, 8 b), 256 threads. Thread: c = tid&63, jg = tid>>6 owns 16 j-pairs.

__global__ void __launch_bounds__(256) passA_kernel(const float* __restrict__ x,
                                                    const float* __restrict__ xin) {
    int b = blockIdx.y;
    int n0 = blockIdx.x * 512;
    int tid = threadIdx.x;
    int c = tid & 63;
    int jg = tid >> 6;
    int nw = c;        // basis-gen: n within tile
    int part = jg;     // basis-gen: which 16-m segment (0,1 = y; 2,3 = x)

    __shared__ float V[NT * VSTRIDE];

    unsigned long long acc[16];
#pragma unroll
    for (int s = 0; s < 16; s++) acc[s] = 0ull;

    for (int t0 = 0; t0 < 512; t0 += NT) {
        // --- basis generation for this n-tile ---
        {
            int n = n0 + t0 + nw;
            float p = __ldg(&xin[(b * NN + n) * 2 + (part >> 1)]);
            float cs, ss;
            sc2pi(p, ss, cs);  // step = e^{i 2 pi p}
            float c0, s0;
            if ((part & 1) == 0) {
                c0 = 1.0f; s0 = 0.0f;          // m = 0
            } else {
                float t = p * 16.0f;
                t -= floorf(t);
                sc2pi(t, s0, c0);              // m = 16
            }
            float* row = &V[nw * VSTRIDE + part * 32];
            row[0] = c0;
            row[1] = s0;
#pragma unroll
            for (int m = 1; m < 16; m++) {
                float c1 = c0 * cs - s0 * ss;
                float s1 = fmaf(s0, cs, c0 * ss);
                row[2 * m] = c1;
                row[2 * m + 1] = s1;
                c0 = c1;
                s0 = s1;
            }
        }
        __syncthreads();

        // --- accumulate over the tile ---
        const float* xr = x + (size_t)(b * CC + c) * NN + n0 + t0;
#pragma unroll 2
        for (int nn = 0; nn < NT; nn++) {
            float xv = __ldg(xr + nn);
            unsigned long long xd = pack2(xv, xv);
            const ulonglong2* vp =
                reinterpret_cast<const ulonglong2*>(&V[nn * VSTRIDE + jg * 32]);
#pragma unroll
            for (int t = 0; t < 8; t++) {
                ulonglong2 vv = vp[t];
                ffma2(acc[2 * t], xd, vv.x);
                ffma2(acc[2 * t + 1], xd, vv.y);
            }
        }
        __syncthreads();
    }

    // cross-block reduction over n-chunks
    float* Fp = &g_F[(b * CC + c) * JJ + jg * 32];
#pragma unroll
    for (int s = 0; s < 16; s++) {
        float lo, hi;
        unpack2(acc[s], lo, hi);
        atomicAdd(&Fp[2 * s], lo);
        atomicAdd(&Fp[2 * s + 1], hi);
    }
}

// ---------- Pass B: channel mixing (tiny GEMMs) ----------
// fty = C - iS ; my = sum_i fty_i * W_io ; G = (64*my_r, -64*my_i)
// grid (64 jp, 8 b), 64 threads (one per o)

__global__ void __launch_bounds__(64) passB_kernel(const float* __restrict__ w1,
                                                   const float* __restrict__ w2) {
    int b = blockIdx.y;
    int jp = blockIdx.x;
    int o = threadIdx.x;

    __shared__ float Cv[64], Sv[64];
    Cv[o] = g_F[(b * CC + o) * JJ + 2 * jp];       // reuse thread index as i for loads
    Sv[o] = g_F[(b * CC + o) * JJ + 2 * jp + 1];
    __syncthreads();

    const float* w = (jp < 32) ? w1 : w2;  // jp<32: y-branch (w1/M2), else x-branch (w2/M1)
    int m = jp & 31;

    float ar = 0.0f, ai = 0.0f;
#pragma unroll 8
    for (int i = 0; i < 64; i++) {
        float2 wv = *reinterpret_cast<const float2*>(&w[((i * 64 + o) * 32 + m) * 2]);
        ar = fmaf(Cv[i], wv.x, ar);
        ar = fmaf(Sv[i], wv.y, ar);
        ai = fmaf(Cv[i], wv.y, ai);
        ai = fmaf(-Sv[i], wv.x, ai);
    }
    g_G[((b * KP + jp) * CC + o) * 2] = 64.0f * ar;
    g_G[((b * KP + jp) * CC + o) * 2 + 1] = -64.0f * ai;
}

// ---------- Pass C: out[b,o,n] = sum_k G[b,k,o] * basis(x_out)[n,k] ----------
// grid (32 chunks, 8 b), 256 threads. Thread tile 4o x 4n, k-pairs in f32x2 lanes.

__global__ void __launch_bounds__(256) passC_kernel(const float* __restrict__ xout,
                                                    float* __restrict__ out) {
    int b = blockIdx.y;
    int n0 = blockIdx.x * 512;
    int tid = threadIdx.x;
    int tx = tid & 15;   // n-quad
    int ty = tid >> 4;   // o-quad
    int nw = tid & 63;
    int part = tid >> 6;

    __shared__ float U[NT * VSTRIDE];  // [kp][2n] transposed basis tile
    const float* Gb = &g_G[(size_t)b * KP * CC * 2];

    for (int t0 = 0; t0 < 512; t0 += NT) {
        // --- basis generation (transposed layout: U[kp][2*nw] = (cos, sin)) ---
        {
            int n = n0 + t0 + nw;
            float p = __ldg(&xout[(b * NN + n) * 2 + (part >> 1)]);
            float cs, ss;
            sc2pi(p, ss, cs);
            float c0, s0;
            if ((part & 1) == 0) {
                c0 = 1.0f; s0 = 0.0f;
            } else {
                float t = p * 16.0f;
                t -= floorf(t);
                sc2pi(t, s0, c0);
            }
            int kp0 = part * 16;
#pragma unroll
            for (int ml = 0; ml < 16; ml++) {
                if (ml > 0) {
                    float c1 = c0 * cs - s0 * ss;
                    float s1 = fmaf(s0, cs, c0 * ss);
                    c0 = c1;
                    s0 = s1;
                }
                *reinterpret_cast<float2*>(&U[(kp0 + ml) * VSTRIDE + 2 * nw]) =
                    make_float2(c0, s0);
            }
        }
        __syncthreads();

        unsigned long long acc[16];
#pragma unroll
        for (int s = 0; s < 16; s++) acc[s] = 0ull;

#pragma unroll 2
        for (int kp = 0; kp < KP; kp++) {
            ulonglong2 ga =
                __ldg(reinterpret_cast<const ulonglong2*>(&Gb[kp * CC * 2 + ty * 8]));
            ulonglong2 gb =
                __ldg(reinterpret_cast<const ulonglong2*>(&Gb[kp * CC * 2 + ty * 8 + 4]));
            ulonglong2 ua =
                *reinterpret_cast<const ulonglong2*>(&U[kp * VSTRIDE + tx * 8]);
            ulonglong2 ub =
                *reinterpret_cast<const ulonglong2*>(&U[kp * VSTRIDE + tx * 8 + 4]);
            unsigned long long g[4] = {ga.x, ga.y, gb.x, gb.y};
            unsigned long long u[4] = {ua.x, ua.y, ub.x, ub.y};
#pragma unroll
            for (int i2 = 0; i2 < 4; i2++)
#pragma unroll
                for (int j2 = 0; j2 < 4; j2++) ffma2(acc[i2 * 4 + j2], g[i2], u[j2]);
        }
        __syncthreads();  // before next tile overwrites U

        // --- write 4o x 4n outputs (horizontal add of the two f32x2 lanes) ---
#pragma unroll
        for (int i2 = 0; i2 < 4; i2++) {
            float lo, hi;
            float4 r;
            unpack2(acc[i2 * 4 + 0], lo, hi); r.x = lo + hi;
            unpack2(acc[i2 * 4 + 1], lo, hi); r.y = lo + hi;
            unpack2(acc[i2 * 4 + 2], lo, hi); r.z = lo + hi;
            unpack2(acc[i2 * 4 + 3], lo, hi); r.w = lo + hi;
            *reinterpret_cast<float4*>(
                &out[(size_t)(b * CC + ty * 4 + i2) * NN + n0 + t0 + tx * 4]) = r;
        }
    }
}

// ---------- launch ----------

extern "C" void kernel_launch(void* const* d_in, const int* in_sizes, int n_in,
                              void* d_out, int out_size) {
    const float* x    = (const float*)d_in[0];
    const float* xin  = (const float*)d_in[1];
    const float* xout = (const float*)d_in[2];
    const float* w1   = (const float*)d_in[3];
    const float* w2   = (const float*)d_in[4];
    float* out = (float*)d_out;

    zeroF_kernel<<<(BB * CC * JJ) / 256, 256>>>();
    passA_kernel<<<dim3(32, BB), 256>>>(x, xin);
    passB_kernel<<<dim3(KP, BB), 64>>>(w1, w2);
    passC_kernel<<<dim3(32, BB), 256>>>(xout, out);
}

// round 5
// speedup vs baseline: 1.4065x; 1.4065x over previous
#include <cuda_runtime.h>
#include <cstdint>

#define BB 8
#define CC 64
#define NN 16384
#define JJ 128      // 2 branches * 32 m * (cos,sin)
#define KP 64       // j-pairs (k-pairs in pass C)
#define USTRIDE 132 // passC basis row stride (floats), 16B-aligned rows
#define VSTRIDE 132 // passA basis row stride (floats)
#define XSTRIDE 66  // passA x-tile row stride (floats)

// Inter-kernel scratch (static __device__ — no allocation)
__device__ float g_F[BB * CC * JJ];      // pass A output: [b][c][j]
__device__ float g_G[BB * KP * CC * 2];  // pass B output: [b][kp][o][(re,-im)]

// ---------- helpers ----------

// returns (sin(2*pi*t), cos(2*pi*t)) for t in [0,1): shift to [-pi,pi) for accuracy
__device__ __forceinline__ void sc2pi(float t, float& s, float& c) {
    float a = fmaf(t, 6.28318530718f, -3.14159265359f);
    float ss, cc;
    __sincosf(a, &ss, &cc);
    s = -ss;
    c = -cc;
}

__device__ __forceinline__ unsigned long long pack2(float lo, float hi) {
    unsigned long long r;
    asm("mov.b64 %0, {%1, %2};" : "=l"(r) : "f"(lo), "f"(hi));
    return r;
}

__device__ __forceinline__ void unpack2(unsigned long long v, float& lo, float& hi) {
    asm("mov.b64 {%0, %1}, %2;" : "=f"(lo), "=f"(hi) : "l"(v));
}

// packed f32x2 FMA: d = a*b + d (lanewise)
__device__ __forceinline__ void ffma2(unsigned long long& d, unsigned long long a,
                                      unsigned long long b) {
    asm("fma.rn.f32x2 %0, %1, %2, %0;" : "+l"(d) : "l"(a), "l"(b));
}

// ---------- zero scratch ----------

__global__ void zeroF_kernel() {
    g_F[blockIdx.x * 256 + threadIdx.x] = 0.0f;
}

// ---------- Pass A: F[b,c,j] = sum_n x[b,c,n] * basis(x_in)[n,j] ----------
// grid (64 chunks, 8 b), 256 threads. Thread: cc2 = tid&31 handles c = {cc2, cc2+32},
// jg = tid>>5 handles 8 j-pairs. n-tile = 32, x staged transposed in smem.

__global__ void __launch_bounds__(256) passA_kernel(const float* __restrict__ x,
                                                    const float* __restrict__ xin) {
    int b = blockIdx.y;
    int n0 = blockIdx.x * 256;
    int tid = threadIdx.x;
    int cc2 = tid & 31;
    int jg = tid >> 5;           // 0..7: pairs jg*8 .. jg*8+7 (floats jg*16..+15)
    int nw = tid & 31;           // gen: n within tile
    int part = tid >> 5;         // gen: 8 segments of 8 m (part>>2 = coord)

    __shared__ float V[32 * VSTRIDE];   // basis tile [nn][128 j floats]
    __shared__ float Xs[32 * XSTRIDE];  // x tile transposed [nn][c]

    unsigned long long accA[8], accB[8];
#pragma unroll
    for (int s = 0; s < 8; s++) { accA[s] = 0ull; accB[s] = 0ull; }

    const float* xb = x + (size_t)b * CC * NN;

    for (int t0 = 0; t0 < 256; t0 += 32) {
        int n0t = n0 + t0;
        __syncthreads();

        // --- stage x tile transposed: Xs[nn][c] = x[b][c][n0t+nn] ---
#pragma unroll
        for (int k = 0; k < 2; k++) {
            int idx = tid + k * 256;
            int c = idx >> 3;
            int nq = idx & 7;  // float4 index: n = nq*4 .. nq*4+3
            float4 v = __ldg(reinterpret_cast<const float4*>(
                xb + (size_t)c * NN + n0t + nq * 4));
            Xs[(nq * 4 + 0) * XSTRIDE + c] = v.x;
            Xs[(nq * 4 + 1) * XSTRIDE + c] = v.y;
            Xs[(nq * 4 + 2) * XSTRIDE + c] = v.z;
            Xs[(nq * 4 + 3) * XSTRIDE + c] = v.w;
        }

        // --- basis generation for this n-tile (8 segments x 8 m) ---
        {
            int n = n0t + nw;
            int coord = part >> 2;
            int ms = (part & 3) * 8;
            float p = __ldg(&xin[(b * NN + n) * 2 + coord]);
            float cs, ss;
            sc2pi(p, ss, cs);  // step = e^{i 2 pi p}
            float c0, s0;
            if (ms == 0) {
                c0 = 1.0f; s0 = 0.0f;
            } else {
                float t = p * (float)ms;
                t -= floorf(t);
                sc2pi(t, s0, c0);
            }
            float* row = &V[nw * VSTRIDE + coord * 64 + ms * 2];
            row[0] = c0;
            row[1] = s0;
#pragma unroll
            for (int m = 1; m < 8; m++) {
                float c1 = c0 * cs - s0 * ss;
                float s1 = fmaf(s0, cs, c0 * ss);
                row[2 * m] = c1;
                row[2 * m + 1] = s1;
                c0 = c1;
                s0 = s1;
            }
        }
        __syncthreads();

        // --- accumulate over the tile ---
#pragma unroll 4
        for (int nn = 0; nn < 32; nn++) {
            float xa = Xs[nn * XSTRIDE + cc2];
            float xc = Xs[nn * XSTRIDE + cc2 + 32];
            unsigned long long xda = pack2(xa, xa);
            unsigned long long xdc = pack2(xc, xc);
            const ulonglong2* vp =
                reinterpret_cast<const ulonglong2*>(&V[nn * VSTRIDE + jg * 16]);
#pragma unroll
            for (int t = 0; t < 4; t++) {
                ulonglong2 vv = vp[t];
                ffma2(accA[2 * t], xda, vv.x);
                ffma2(accA[2 * t + 1], xda, vv.y);
                ffma2(accB[2 * t], xdc, vv.x);
                ffma2(accB[2 * t + 1], xdc, vv.y);
            }
        }
    }

    // cross-block reduction over n-chunks
    float* FpA = &g_F[(b * CC + cc2) * JJ + jg * 16];
    float* FpB = FpA + 32 * JJ;
#pragma unroll
    for (int s = 0; s < 8; s++) {
        float lo, hi;
        unpack2(accA[s], lo, hi);
        atomicAdd(&FpA[2 * s], lo);
        atomicAdd(&FpA[2 * s + 1], hi);
        unpack2(accB[s], lo, hi);
        atomicAdd(&FpB[2 * s], lo);
        atomicAdd(&FpB[2 * s + 1], hi);
    }
}

// ---------- Pass B: channel mixing (tiny GEMMs) ----------
// fty = C - iS ; my = sum_i fty_i * W_io ; G = (64*my_r, -64*my_i)
// grid (64 jp, 8 b), 64 threads (one per o)

__global__ void __launch_bounds__(64) passB_kernel(const float* __restrict__ w1,
                                                   const float* __restrict__ w2) {
    int b = blockIdx.y;
    int jp = blockIdx.x;
    int o = threadIdx.x;

    __shared__ float Cv[64], Sv[64];
    Cv[o] = g_F[(b * CC + o) * JJ + 2 * jp];  // thread index doubles as i for loads
    Sv[o] = g_F[(b * CC + o) * JJ + 2 * jp + 1];
    __syncthreads();

    const float* w = (jp < 32) ? w1 : w2;  // jp<32: y-branch (w1), else x-branch (w2)
    int m = jp & 31;

    float ar = 0.0f, ai = 0.0f;
#pragma unroll 8
    for (int i = 0; i < 64; i++) {
        float2 wv = *reinterpret_cast<const float2*>(&w[((i * 64 + o) * 32 + m) * 2]);
        ar = fmaf(Cv[i], wv.x, ar);
        ar = fmaf(Sv[i], wv.y, ar);
        ai = fmaf(Cv[i], wv.y, ai);
        ai = fmaf(-Sv[i], wv.x, ai);
    }
    g_G[((b * KP + jp) * CC + o) * 2] = 64.0f * ar;
    g_G[((b * KP + jp) * CC + o) * 2 + 1] = -64.0f * ai;
}

// ---------- Pass C: out[b,o,n] = sum_k G[b,k,o] * basis(x_out)[n,k] ----------
// grid (128 chunks, 8 b), 128 threads. Thread tile 4o x 8n; warp = 8 tx * 4 ty so
// each U LDS.128 is one wavefront and G loads dedup 4-way.

__global__ void __launch_bounds__(128) passC_kernel(const float* __restrict__ xout,
                                                    float* __restrict__ out) {
    int b = blockIdx.y;
    int n0 = blockIdx.x * 128;
    int tid = threadIdx.x;
    int tx = tid & 7;    // n-oct: n = tx*8 .. tx*8+7 within tile
    int ty = tid >> 3;   // o-quad: o = ty*4 .. ty*4+3
    int nw = tid & 63;   // gen: n within tile
    int part = tid >> 6; // gen: coord (0=y rows 0..31, 1=x rows 32..63)

    __shared__ float U[64 * USTRIDE];  // [kp][2n] transposed basis tile
    const float* Gb = &g_G[(size_t)b * KP * CC * 2];

    for (int t0 = 0; t0 < 128; t0 += 64) {
        __syncthreads();
        // --- basis generation: U[kp][2*nw] = (cos, sin), 32 kp rows per gen thread ---
        {
            int n = n0 + t0 + nw;
            float p = __ldg(&xout[(b * NN + n) * 2 + part]);
            float cs, ss;
            sc2pi(p, ss, cs);
            float c0 = 1.0f, s0 = 0.0f;
#pragma unroll
            for (int half = 0; half < 2; half++) {
                if (half == 1) {
                    float t = p * 16.0f;
                    t -= floorf(t);
                    sc2pi(t, s0, c0);
                }
                int kp0 = part * 32 + half * 16;
#pragma unroll
                for (int ml = 0; ml < 16; ml++) {
                    if (ml > 0) {
                        float c1 = c0 * cs - s0 * ss;
                        float s1 = fmaf(s0, cs, c0 * ss);
                        c0 = c1;
                        s0 = s1;
                    }
                    *reinterpret_cast<float2*>(&U[(kp0 + ml) * USTRIDE + 2 * nw]) =
                        make_float2(c0, s0);
                }
            }
        }
        __syncthreads();

        unsigned long long acc[32];
#pragma unroll
        for (int s = 0; s < 32; s++) acc[s] = 0ull;

#pragma unroll 2
        for (int kp = 0; kp < KP; kp++) {
            const ulonglong2* up =
                reinterpret_cast<const ulonglong2*>(&U[kp * USTRIDE + tx * 16]);
            ulonglong2 u0 = up[0], u1 = up[1], u2 = up[2], u3 = up[3];
            const ulonglong2* gp =
                reinterpret_cast<const ulonglong2*>(&Gb[kp * CC * 2 + ty * 8]);
            ulonglong2 g0 = __ldg(gp), g1 = __ldg(gp + 1);
            unsigned long long g[4] = {g0.x, g0.y, g1.x, g1.y};
            unsigned long long u[8] = {u0.x, u0.y, u1.x, u1.y,
                                       u2.x, u2.y, u3.x, u3.y};
#pragma unroll
            for (int i2 = 0; i2 < 4; i2++)
#pragma unroll
                for (int j2 = 0; j2 < 8; j2++) ffma2(acc[i2 * 8 + j2], g[i2], u[j2]);
        }

        // --- write 4o x 8n outputs (horizontal add of the two f32x2 lanes) ---
#pragma unroll
        for (int i2 = 0; i2 < 4; i2++) {
            float lo, hi;
            float4 r0, r1;
            unpack2(acc[i2 * 8 + 0], lo, hi); r0.x = lo + hi;
            unpack2(acc[i2 * 8 + 1], lo, hi); r0.y = lo + hi;
            unpack2(acc[i2 * 8 + 2], lo, hi); r0.z = lo + hi;
            unpack2(acc[i2 * 8 + 3], lo, hi); r0.w = lo + hi;
            unpack2(acc[i2 * 8 + 4], lo, hi); r1.x = lo + hi;
            unpack2(acc[i2 * 8 + 5], lo, hi); r1.y = lo + hi;
            unpack2(acc[i2 * 8 + 6], lo, hi); r1.z = lo + hi;
            unpack2(acc[i2 * 8 + 7], lo, hi); r1.w = lo + hi;
            float* op = &out[(size_t)(b * CC + ty * 4 + i2) * NN + n0 + t0 + tx * 8];
            reinterpret_cast<float4*>(op)[0] = r0;
            reinterpret_cast<float4*>(op)[1] = r1;
        }
    }
}

// ---------- launch ----------

extern "C" void kernel_launch(void* const* d_in, const int* in_sizes, int n_in,
                              void* d_out, int out_size) {
    const float* x    = (const float*)d_in[0];
    const float* xin  = (const float*)d_in[1];
    const float* xout = (const float*)d_in[2];
    const float* w1   = (const float*)d_in[3];
    const float* w2   = (const float*)d_in[4];
    float* out = (float*)d_out;

    zeroF_kernel<<<(BB * CC * JJ) / 256, 256>>>();
    passA_kernel<<<dim3(64, BB), 256>>>(x, xin);
    passB_kernel<<<dim3(KP, BB), 64>>>(w1, w2);
    passC_kernel<<<dim3(128, BB), 128>>>(xout, out);
}

// round 6
// speedup vs baseline: 1.4080x; 1.0011x over previous
#include <cuda_runtime.h>
#include <cstdint>

#define BB 8
#define CC 64
#define NN 16384
#define JJ 128      // 2 branches * 32 m * (cos,sin)
#define KP 64       // j-pairs (k-pairs in pass C)
#define USTRIDE 132 // passC basis row stride (floats), 16B-aligned rows
#define VSTRIDE 132 // passA basis row stride (floats)
#define XSTRIDE 66  // passA x-tile row stride (floats)

// Inter-kernel scratch (static __device__ — no allocation)
__device__ float g_F[BB * CC * JJ];      // pass A output: [b][c][j]
__device__ float g_G[BB * KP * CC * 2];  // pass B output: [b][kp][o][(re,-im)]

// ---------- helpers ----------

// returns (sin(2*pi*t), cos(2*pi*t)) for t in [0,1): shift to [-pi,pi) for accuracy
__device__ __forceinline__ void sc2pi(float t, float& s, float& c) {
    float a = fmaf(t, 6.28318530718f, -3.14159265359f);
    float ss, cc;
    __sincosf(a, &ss, &cc);
    s = -ss;
    c = -cc;
}

__device__ __forceinline__ unsigned long long pack2(float lo, float hi) {
    unsigned long long r;
    asm("mov.b64 %0, {%1, %2};" : "=l"(r) : "f"(lo), "f"(hi));
    return r;
}

__device__ __forceinline__ void unpack2(unsigned long long v, float& lo, float& hi) {
    asm("mov.b64 {%0, %1}, %2;" : "=f"(lo), "=f"(hi) : "l"(v));
}

// packed f32x2 FMA: d = a*b + d (lanewise)
__device__ __forceinline__ void ffma2(unsigned long long& d, unsigned long long a,
                                      unsigned long long b) {
    asm("fma.rn.f32x2 %0, %1, %2, %0;" : "+l"(d) : "l"(a), "l"(b));
}

// ---------- zero scratch ----------

__global__ void zeroF_kernel() {
    g_F[blockIdx.x * 256 + threadIdx.x] = 0.0f;
}

// ---------- Pass A: F[b,c,j] = sum_n x[b,c,n] * basis(x_in)[n,j] ----------
// grid (64 chunks, 8 b), 256 threads. Thread: cc2 = tid&31 handles c = {cc2, cc2+32},
// jg = tid>>5 handles 8 j-pairs. n-tile = 32, x staged transposed in smem.

__global__ void __launch_bounds__(256) passA_kernel(const float* __restrict__ x,
                                                    const float* __restrict__ xin) {
    int b = blockIdx.y;
    int n0 = blockIdx.x * 256;
    int tid = threadIdx.x;
    int cc2 = tid & 31;
    int jg = tid >> 5;           // 0..7: pairs jg*8 .. jg*8+7 (floats jg*16..+15)
    int nw = tid & 31;           // gen: n within tile
    int part = tid >> 5;         // gen: 8 segments of 8 m (part>>2 = coord)

    __shared__ float V[32 * VSTRIDE];   // basis tile [nn][128 j floats]
    __shared__ float Xs[32 * XSTRIDE];  // x tile transposed [nn][c]

    unsigned long long accA[8], accB[8];
#pragma unroll
    for (int s = 0; s < 8; s++) { accA[s] = 0ull; accB[s] = 0ull; }

    const float* xb = x + (size_t)b * CC * NN;

    for (int t0 = 0; t0 < 256; t0 += 32) {
        int n0t = n0 + t0;
        __syncthreads();

        // --- stage x tile transposed: Xs[nn][c] = x[b][c][n0t+nn] ---
#pragma unroll
        for (int k = 0; k < 2; k++) {
            int idx = tid + k * 256;
            int c = idx >> 3;
            int nq = idx & 7;  // float4 index: n = nq*4 .. nq*4+3
            float4 v = __ldg(reinterpret_cast<const float4*>(
                xb + (size_t)c * NN + n0t + nq * 4));
            Xs[(nq * 4 + 0) * XSTRIDE + c] = v.x;
            Xs[(nq * 4 + 1) * XSTRIDE + c] = v.y;
            Xs[(nq * 4 + 2) * XSTRIDE + c] = v.z;
            Xs[(nq * 4 + 3) * XSTRIDE + c] = v.w;
        }

        // --- basis generation for this n-tile (8 segments x 8 m) ---
        {
            int n = n0t + nw;
            int coord = part >> 2;
            int ms = (part & 3) * 8;
            float p = __ldg(&xin[(b * NN + n) * 2 + coord]);
            float cs, ss;
            sc2pi(p, ss, cs);  // step = e^{i 2 pi p}
            float c0, s0;
            if (ms == 0) {
                c0 = 1.0f; s0 = 0.0f;
            } else {
                float t = p * (float)ms;
                t -= floorf(t);
                sc2pi(t, s0, c0);
            }
            float* row = &V[nw * VSTRIDE + coord * 64 + ms * 2];
            row[0] = c0;
            row[1] = s0;
#pragma unroll
            for (int m = 1; m < 8; m++) {
                float c1 = c0 * cs - s0 * ss;
                float s1 = fmaf(s0, cs, c0 * ss);
                row[2 * m] = c1;
                row[2 * m + 1] = s1;
                c0 = c1;
                s0 = s1;
            }
        }
        __syncthreads();

        // --- accumulate over the tile ---
#pragma unroll 4
        for (int nn = 0; nn < 32; nn++) {
            float xa = Xs[nn * XSTRIDE + cc2];
            float xc = Xs[nn * XSTRIDE + cc2 + 32];
            unsigned long long xda = pack2(xa, xa);
            unsigned long long xdc = pack2(xc, xc);
            const ulonglong2* vp =
                reinterpret_cast<const ulonglong2*>(&V[nn * VSTRIDE + jg * 16]);
#pragma unroll
            for (int t = 0; t < 4; t++) {
                ulonglong2 vv = vp[t];
                ffma2(accA[2 * t], xda, vv.x);
                ffma2(accA[2 * t + 1], xda, vv.y);
                ffma2(accB[2 * t], xdc, vv.x);
                ffma2(accB[2 * t + 1], xdc, vv.y);
            }
        }
    }

    // cross-block reduction over n-chunks
    float* FpA = &g_F[(b * CC + cc2) * JJ + jg * 16];
    float* FpB = FpA + 32 * JJ;
#pragma unroll
    for (int s = 0; s < 8; s++) {
        float lo, hi;
        unpack2(accA[s], lo, hi);
        atomicAdd(&FpA[2 * s], lo);
        atomicAdd(&FpA[2 * s + 1], hi);
        unpack2(accB[s], lo, hi);
        atomicAdd(&FpB[2 * s], lo);
        atomicAdd(&FpB[2 * s + 1], hi);
    }
}

// ---------- Pass B: channel mixing (tiny GEMMs) ----------
// fty = C - iS ; my = sum_i fty_i * W_io ; G = (64*my_r, -64*my_i)
// grid (64 jp, 8 b), 64 threads (one per o)

__global__ void __launch_bounds__(64) passB_kernel(const float* __restrict__ w1,
                                                   const float* __restrict__ w2) {
    int b = blockIdx.y;
    int jp = blockIdx.x;
    int o = threadIdx.x;

    __shared__ float Cv[64], Sv[64];
    Cv[o] = g_F[(b * CC + o) * JJ + 2 * jp];  // thread index doubles as i for loads
    Sv[o] = g_F[(b * CC + o) * JJ + 2 * jp + 1];
    __syncthreads();

    const float* w = (jp < 32) ? w1 : w2;  // jp<32: y-branch (w1), else x-branch (w2)
    int m = jp & 31;

    float ar = 0.0f, ai = 0.0f;
#pragma unroll 8
    for (int i = 0; i < 64; i++) {
        float2 wv = *reinterpret_cast<const float2*>(&w[((i * 64 + o) * 32 + m) * 2]);
        ar = fmaf(Cv[i], wv.x, ar);
        ar = fmaf(Sv[i], wv.y, ar);
        ai = fmaf(Cv[i], wv.y, ai);
        ai = fmaf(-Sv[i], wv.x, ai);
    }
    g_G[((b * KP + jp) * CC + o) * 2] = 64.0f * ar;
    g_G[((b * KP + jp) * CC + o) * 2 + 1] = -64.0f * ai;
}

// ---------- Pass C: out[b,o,n] = sum_k G[b,k,o] * basis(x_out)[n,k] ----------
// grid (128 chunks, 8 b), 128 threads. Thread tile 4o x 8n; warp = 8 tx * 4 ty so
// each U LDS.128 is one wavefront and G loads dedup 4-way.

__global__ void __launch_bounds__(128) passC_kernel(const float* __restrict__ xout,
                                                    float* __restrict__ out) {
    int b = blockIdx.y;
    int n0 = blockIdx.x * 128;
    int tid = threadIdx.x;
    int tx = tid & 7;    // n-oct: n = tx*8 .. tx*8+7 within tile
    int ty = tid >> 3;   // o-quad: o = ty*4 .. ty*4+3
    int nw = tid & 63;   // gen: n within tile
    int part = tid >> 6; // gen: coord (0=y rows 0..31, 1=x rows 32..63)

    __shared__ float U[64 * USTRIDE];  // [kp][2n] transposed basis tile
    const float* Gb = &g_G[(size_t)b * KP * CC * 2];

    for (int t0 = 0; t0 < 128; t0 += 64) {
        __syncthreads();
        // --- basis generation: U[kp][2*nw] = (cos, sin), 32 kp rows per gen thread ---
        {
            int n = n0 + t0 + nw;
            float p = __ldg(&xout[(b * NN + n) * 2 + part]);
            float cs, ss;
            sc2pi(p, ss, cs);
            float c0 = 1.0f, s0 = 0.0f;
#pragma unroll
            for (int half = 0; half < 2; half++) {
                if (half == 1) {
                    float t = p * 16.0f;
                    t -= floorf(t);
                    sc2pi(t, s0, c0);
                }
                int kp0 = part * 32 + half * 16;
#pragma unroll
                for (int ml = 0; ml < 16; ml++) {
                    if (ml > 0) {
                        float c1 = c0 * cs - s0 * ss;
                        float s1 = fmaf(s0, cs, c0 * ss);
                        c0 = c1;
                        s0 = s1;
                    }
                    *reinterpret_cast<float2*>(&U[(kp0 + ml) * USTRIDE + 2 * nw]) =
                        make_float2(c0, s0);
                }
            }
        }
        __syncthreads();

        unsigned long long acc[32];
#pragma unroll
        for (int s = 0; s < 32; s++) acc[s] = 0ull;

#pragma unroll 2
        for (int kp = 0; kp < KP; kp++) {
            const ulonglong2* up =
                reinterpret_cast<const ulonglong2*>(&U[kp * USTRIDE + tx * 16]);
            ulonglong2 u0 = up[0], u1 = up[1], u2 = up[2], u3 = up[3];
            const ulonglong2* gp =
                reinterpret_cast<const ulonglong2*>(&Gb[kp * CC * 2 + ty * 8]);
            ulonglong2 g0 = __ldg(gp), g1 = __ldg(gp + 1);
            unsigned long long g[4] = {g0.x, g0.y, g1.x, g1.y};
            unsigned long long u[8] = {u0.x, u0.y, u1.x, u1.y,
                                       u2.x, u2.y, u3.x, u3.y};
#pragma unroll
            for (int i2 = 0; i2 < 4; i2++)
#pragma unroll
                for (int j2 = 0; j2 < 8; j2++) ffma2(acc[i2 * 8 + j2], g[i2], u[j2]);
        }

        // --- write 4o x 8n outputs (horizontal add of the two f32x2 lanes) ---
#pragma unroll
        for (int i2 = 0; i2 < 4; i2++) {
            float lo, hi;
            float4 r0, r1;
            unpack2(acc[i2 * 8 + 0], lo, hi); r0.x = lo + hi;
            unpack2(acc[i2 * 8 + 1], lo, hi); r0.y = lo + hi;
            unpack2(acc[i2 * 8 + 2], lo, hi); r0.z = lo + hi;
            unpack2(acc[i2 * 8 + 3], lo, hi); r0.w = lo + hi;
            unpack2(acc[i2 * 8 + 4], lo, hi); r1.x = lo + hi;
            unpack2(acc[i2 * 8 + 5], lo, hi); r1.y = lo + hi;
            unpack2(acc[i2 * 8 + 6], lo, hi); r1.z = lo + hi;
            unpack2(acc[i2 * 8 + 7], lo, hi); r1.w = lo + hi;
            float* op = &out[(size_t)(b * CC + ty * 4 + i2) * NN + n0 + t0 + tx * 8];
            reinterpret_cast<float4*>(op)[0] = r0;
            reinterpret_cast<float4*>(op)[1] = r1;
        }
    }
}

// ---------- launch ----------

extern "C" void kernel_launch(void* const* d_in, const int* in_sizes, int n_in,
                              void* d_out, int out_size) {
    const float* x    = (const float*)d_in[0];
    const float* xin  = (const float*)d_in[1];
    const float* xout = (const float*)d_in[2];
    const float* w1   = (const float*)d_in[3];
    const float* w2   = (const float*)d_in[4];
    float* out = (float*)d_out;

    zeroF_kernel<<<(BB * CC * JJ) / 256, 256>>>();
    passA_kernel<<<dim3(64, BB), 256>>>(x, xin);
    passB_kernel<<<dim3(KP, BB), 64>>>(w1, w2);
    passC_kernel<<<dim3(128, BB), 128>>>(xout, out);
}

// round 7
// speedup vs baseline: 2.1088x; 1.4977x over previous
#include <cuda_runtime.h>
#include <cstdint>

#define BB 8
#define CC 64
#define NN 16384
#define JJ 128      // 2 branches * 32 m * (cos,sin)
#define KP 64       // j-pairs (k-pairs in pass C)
#define USTRIDE 132 // passC basis row stride (floats)
#define VSTRIDE 132 // passA basis row stride (floats)
#define XSTRIDE 66  // passA x-tile row stride (floats)
#define NCHUNK 64   // passA n-chunks (blocks per b)

// Inter-kernel scratch (static __device__ — no allocation)
__device__ float g_Fp[BB * NCHUNK * CC * JJ];  // passA partials [b][chunk][c][j]
__device__ float g_F[BB * CC * JJ];            // reduced F
__device__ float g_G[BB * KP * CC * 2];        // passB output [b][kp][o][(re,-im)]

// ---------- helpers ----------

// returns (sin(2*pi*t), cos(2*pi*t)) for t in [0,1): shift to [-pi,pi) for accuracy
__device__ __forceinline__ void sc2pi(float t, float& s, float& c) {
    float a = fmaf(t, 6.28318530718f, -3.14159265359f);
    float ss, cc;
    __sincosf(a, &ss, &cc);
    s = -ss;
    c = -cc;
}

__device__ __forceinline__ unsigned long long pack2(float lo, float hi) {
    unsigned long long r;
    asm("mov.b64 %0, {%1, %2};" : "=l"(r) : "f"(lo), "f"(hi));
    return r;
}

__device__ __forceinline__ void unpack2(unsigned long long v, float& lo, float& hi) {
    asm("mov.b64 {%0, %1}, %2;" : "=f"(lo), "=f"(hi) : "l"(v));
}

// packed f32x2 FMA: d = a*b + d (lanewise)
__device__ __forceinline__ void ffma2(unsigned long long& d, unsigned long long a,
                                      unsigned long long b) {
    asm("fma.rn.f32x2 %0, %1, %2, %0;" : "+l"(d) : "l"(a), "l"(b));
}

// ---------- Pass A: partial F over one n-chunk of 256 ----------
// grid (64 chunks, 8 b), 256 threads. Thread: cc2 = tid&31 handles c = {cc2, cc2+32},
// jg = tid>>5 handles 8 j-pairs. n-tile = 32; x staged transposed; next tile prefetched.

__global__ void __launch_bounds__(256) passA_kernel(const float* __restrict__ x,
                                                    const float* __restrict__ xin) {
    int b = blockIdx.y;
    int chunk = blockIdx.x;
    int n0 = chunk * 256;
    int tid = threadIdx.x;
    int cc2 = tid & 31;
    int jg = tid >> 5;           // 0..7: j-pairs jg*8..jg*8+7 (floats jg*16..+15)
    int nw = tid & 31;           // gen: n within tile
    int part = tid >> 5;         // gen: 8 segments of 8 m (part>>2 = coord)
    int coord = part >> 2;
    int ms = (part & 3) * 8;
    int cst = tid >> 3;          // staging c (0..31; +32 for second read)
    int nqs = tid & 7;           // staging float4 index

    __shared__ float V[32 * VSTRIDE];   // basis tile [nn][128 j floats]
    __shared__ float Xs[32 * XSTRIDE];  // x tile transposed [nn][c]

    unsigned long long accA[8], accB[8];
#pragma unroll
    for (int s = 0; s < 8; s++) { accA[s] = 0ull; accB[s] = 0ull; }

    const float* xb = x + (size_t)b * CC * NN;

    // prefetch tile 0
    float4 xr0 = __ldg(reinterpret_cast<const float4*>(xb + (size_t)cst * NN + n0 + nqs * 4));
    float4 xr1 = __ldg(reinterpret_cast<const float4*>(xb + (size_t)(cst + 32) * NN + n0 + nqs * 4));
    float pin = __ldg(&xin[(b * NN + n0 + nw) * 2 + coord]);

    for (int t = 0; t < 8; t++) {
        // --- gen compute for this tile (uses prefetched pin) ---
        float gc[8], gs[8];
        {
            float cs, ss;
            sc2pi(pin, ss, cs);  // step = e^{i 2 pi p}
            float c0, s0;
            if (ms == 0) {
                c0 = 1.0f; s0 = 0.0f;
            } else {
                float tt = pin * (float)ms;
                tt -= floorf(tt);
                sc2pi(tt, s0, c0);
            }
            gc[0] = c0; gs[0] = s0;
#pragma unroll
            for (int m = 1; m < 8; m++) {
                float c1 = c0 * cs - s0 * ss;
                float s1 = fmaf(s0, cs, c0 * ss);
                gc[m] = c1; gs[m] = s1;
                c0 = c1; s0 = s1;
            }
        }
        __syncthreads();  // previous tile's reads done; safe to overwrite

        // --- store staged x (transposed) and basis rows ---
        Xs[(nqs * 4 + 0) * XSTRIDE + cst] = xr0.x;
        Xs[(nqs * 4 + 1) * XSTRIDE + cst] = xr0.y;
        Xs[(nqs * 4 + 2) * XSTRIDE + cst] = xr0.z;
        Xs[(nqs * 4 + 3) * XSTRIDE + cst] = xr0.w;
        Xs[(nqs * 4 + 0) * XSTRIDE + cst + 32] = xr1.x;
        Xs[(nqs * 4 + 1) * XSTRIDE + cst + 32] = xr1.y;
        Xs[(nqs * 4 + 2) * XSTRIDE + cst + 32] = xr1.z;
        Xs[(nqs * 4 + 3) * XSTRIDE + cst + 32] = xr1.w;
        {
            float* row = &V[nw * VSTRIDE + coord * 64 + ms * 2];
#pragma unroll
            for (int m = 0; m < 8; m++) {
                row[2 * m] = gc[m];
                row[2 * m + 1] = gs[m];
            }
        }
        __syncthreads();

        // --- prefetch next tile while computing ---
        if (t < 7) {
            int n0n = n0 + (t + 1) * 32;
            xr0 = __ldg(reinterpret_cast<const float4*>(xb + (size_t)cst * NN + n0n + nqs * 4));
            xr1 = __ldg(reinterpret_cast<const float4*>(xb + (size_t)(cst + 32) * NN + n0n + nqs * 4));
            pin = __ldg(&xin[(b * NN + n0n + nw) * 2 + coord]);
        }

        // --- accumulate over the tile ---
#pragma unroll 4
        for (int nn = 0; nn < 32; nn++) {
            float xa = Xs[nn * XSTRIDE + cc2];
            float xc = Xs[nn * XSTRIDE + cc2 + 32];
            unsigned long long xda = pack2(xa, xa);
            unsigned long long xdc = pack2(xc, xc);
            const ulonglong2* vp =
                reinterpret_cast<const ulonglong2*>(&V[nn * VSTRIDE + jg * 16]);
#pragma unroll
            for (int tt = 0; tt < 4; tt++) {
                ulonglong2 vv = vp[tt];
                ffma2(accA[2 * tt], xda, vv.x);
                ffma2(accA[2 * tt + 1], xda, vv.y);
                ffma2(accB[2 * tt], xdc, vv.x);
                ffma2(accB[2 * tt + 1], xdc, vv.y);
            }
        }
    }

    // --- write partials (no atomics): g_Fp[b][chunk][c][jg*16 .. +15] ---
    size_t baseA = ((size_t)(b * NCHUNK + chunk) * CC + cc2) * JJ + jg * 16;
    ulonglong2* pA = reinterpret_cast<ulonglong2*>(&g_Fp[baseA]);
    ulonglong2* pB = reinterpret_cast<ulonglong2*>(&g_Fp[baseA + 32 * JJ]);
#pragma unroll
    for (int tt = 0; tt < 4; tt++) {
        pA[tt] = make_ulonglong2(accA[2 * tt], accA[2 * tt + 1]);
        pB[tt] = make_ulonglong2(accB[2 * tt], accB[2 * tt + 1]);
    }
}

// ---------- reduce partials: g_F[b][cj] = sum_chunk g_Fp[b][chunk][cj] ----------
// grid (8 segs, 8 b), 256 threads, 4 floats (1 float4) per thread; fully coalesced.

__global__ void __launch_bounds__(256) reduceF_kernel() {
    int b = blockIdx.y;
    int cj0 = blockIdx.x * 1024 + threadIdx.x * 4;  // 8 segs * 1024 = 8192
    const float4* src = reinterpret_cast<const float4*>(
        &g_Fp[(size_t)b * NCHUNK * CC * JJ + cj0]);
    float4 s = make_float4(0.f, 0.f, 0.f, 0.f);
#pragma unroll 8
    for (int ch = 0; ch < NCHUNK; ch++) {
        float4 v = src[ch * (CC * JJ / 4)];
        s.x += v.x; s.y += v.y; s.z += v.z; s.w += v.w;
    }
    *reinterpret_cast<float4*>(&g_F[(size_t)b * CC * JJ + cj0]) = s;
}

// ---------- Pass B: channel mixing (tiny GEMMs) ----------
// grid (64 jp, 8 b), 64 threads (one per o)

__global__ void __launch_bounds__(64) passB_kernel(const float* __restrict__ w1,
                                                   const float* __restrict__ w2) {
    int b = blockIdx.y;
    int jp = blockIdx.x;
    int o = threadIdx.x;

    __shared__ float Cv[64], Sv[64];
    Cv[o] = g_F[(b * CC + o) * JJ + 2 * jp];  // thread index doubles as i for loads
    Sv[o] = g_F[(b * CC + o) * JJ + 2 * jp + 1];
    __syncthreads();

    const float* w = (jp < 32) ? w1 : w2;  // jp<32: y-branch (w1), else x-branch (w2)
    int m = jp & 31;

    float ar = 0.0f, ai = 0.0f;
#pragma unroll 8
    for (int i = 0; i < 64; i++) {
        float2 wv = *reinterpret_cast<const float2*>(&w[((i * 64 + o) * 32 + m) * 2]);
        ar = fmaf(Cv[i], wv.x, ar);
        ar = fmaf(Sv[i], wv.y, ar);
        ai = fmaf(Cv[i], wv.y, ai);
        ai = fmaf(-Sv[i], wv.x, ai);
    }
    g_G[((b * KP + jp) * CC + o) * 2] = 64.0f * ar;
    g_G[((b * KP + jp) * CC + o) * 2 + 1] = -64.0f * ai;
}

// ---------- Pass C: out[b,o,n] = sum_k G[b,k,o] * basis(x_out)[n,k] ----------
// grid (128 chunks, 8 b), 128 threads. Thread tile 4o x 8n; warp = 8 tx * 4 ty.
// U row layout is re-tiled so thread tx's 4 chunks sit at t*128B + tx*16B:
// for each t the 8 tx lanes read 128B contiguous -> conflict-free LDS.128.

__global__ void __launch_bounds__(128) passC_kernel(const float* __restrict__ xout,
                                                    float* __restrict__ out) {
    int b = blockIdx.y;
    int n0 = blockIdx.x * 128;
    int tid = threadIdx.x;
    int tx = tid & 7;    // n-oct: n = tx*8 .. tx*8+7 within tile
    int ty = tid >> 3;   // o-quad: o = ty*4 .. ty*4+3
    int nw = tid & 63;   // gen: n within tile
    int part = tid >> 6; // gen: coord (0=y -> kp 0..31, 1=x -> kp 32..63)

    // writer-side position for n = nw inside the re-tiled row:
    // chunk index p = t*8 + txw (t = (nw&7)>>1, txw = nw>>3), element e = nw&1
    int txw = nw >> 3;
    int tw = (nw & 7) >> 1;
    int ew = nw & 1;
    int wroff = tw * 32 + txw * 4 + ew * 2;  // float offset within row

    __shared__ float U[64 * USTRIDE];  // [kp][re-tiled 128 floats]
    const float* Gb = &g_G[(size_t)b * KP * CC * 2];

    for (int t0 = 0; t0 < 128; t0 += 64) {
        __syncthreads();
        // --- basis generation: 32 kp rows per gen thread ---
        {
            int n = n0 + t0 + nw;
            float p = __ldg(&xout[(b * NN + n) * 2 + part]);
            float cs, ss;
            sc2pi(p, ss, cs);
            float c0 = 1.0f, s0 = 0.0f;
#pragma unroll
            for (int half = 0; half < 2; half++) {
                if (half == 1) {
                    float tt = p * 16.0f;
                    tt -= floorf(tt);
                    sc2pi(tt, s0, c0);
                }
                int kp0 = part * 32 + half * 16;
#pragma unroll
                for (int ml = 0; ml < 16; ml++) {
                    if (ml > 0) {
                        float c1 = c0 * cs - s0 * ss;
                        float s1 = fmaf(s0, cs, c0 * ss);
                        c0 = c1;
                        s0 = s1;
                    }
                    *reinterpret_cast<float2*>(&U[(kp0 + ml) * USTRIDE + wroff]) =
                        make_float2(c0, s0);
                }
            }
        }
        __syncthreads();

        unsigned long long acc[32];
#pragma unroll
        for (int s = 0; s < 32; s++) acc[s] = 0ull;

#pragma unroll 2
        for (int kp = 0; kp < KP; kp++) {
            const float* ub = &U[kp * USTRIDE + tx * 4];
            ulonglong2 u0 = *reinterpret_cast<const ulonglong2*>(ub);
            ulonglong2 u1 = *reinterpret_cast<const ulonglong2*>(ub + 32);
            ulonglong2 u2 = *reinterpret_cast<const ulonglong2*>(ub + 64);
            ulonglong2 u3 = *reinterpret_cast<const ulonglong2*>(ub + 96);
            const ulonglong2* gp =
                reinterpret_cast<const ulonglong2*>(&Gb[kp * CC * 2 + ty * 8]);
            ulonglong2 g0 = __ldg(gp), g1 = __ldg(gp + 1);
            unsigned long long g[4] = {g0.x, g0.y, g1.x, g1.y};
            unsigned long long u[8] = {u0.x, u0.y, u1.x, u1.y,
                                       u2.x, u2.y, u3.x, u3.y};
#pragma unroll
            for (int i2 = 0; i2 < 4; i2++)
#pragma unroll
                for (int j2 = 0; j2 < 8; j2++) ffma2(acc[i2 * 8 + j2], g[i2], u[j2]);
        }

        // --- write 4o x 8n outputs (horizontal add of the two f32x2 lanes) ---
#pragma unroll
        for (int i2 = 0; i2 < 4; i2++) {
            float lo, hi;
            float4 r0, r1;
            unpack2(acc[i2 * 8 + 0], lo, hi); r0.x = lo + hi;
            unpack2(acc[i2 * 8 + 1], lo, hi); r0.y = lo + hi;
            unpack2(acc[i2 * 8 + 2], lo, hi); r0.z = lo + hi;
            unpack2(acc[i2 * 8 + 3], lo, hi); r0.w = lo + hi;
            unpack2(acc[i2 * 8 + 4], lo, hi); r1.x = lo + hi;
            unpack2(acc[i2 * 8 + 5], lo, hi); r1.y = lo + hi;
            unpack2(acc[i2 * 8 + 6], lo, hi); r1.z = lo + hi;
            unpack2(acc[i2 * 8 + 7], lo, hi); r1.w = lo + hi;
            float* op = &out[(size_t)(b * CC + ty * 4 + i2) * NN + n0 + t0 + tx * 8];
            reinterpret_cast<float4*>(op)[0] = r0;
            reinterpret_cast<float4*>(op)[1] = r1;
        }
    }
}

// ---------- launch ----------

extern "C" void kernel_launch(void* const* d_in, const int* in_sizes, int n_in,
                              void* d_out, int out_size) {
    const float* x    = (const float*)d_in[0];
    const float* xin  = (const float*)d_in[1];
    const float* xout = (const float*)d_in[2];
    const float* w1   = (const float*)d_in[3];
    const float* w2   = (const float*)d_in[4];
    float* out = (float*)d_out;

    passA_kernel<<<dim3(NCHUNK, BB), 256>>>(x, xin);
    reduceF_kernel<<<dim3(8, BB), 256>>>();
    passB_kernel<<<dim3(KP, BB), 64>>>(w1, w2);
    passC_kernel<<<dim3(128, BB), 128>>>(xout, out);
}